// round 13
// baseline (speedup 1.0000x reference)
#include <cuda_runtime.h>
#include <cstdint>
#include <math.h>

#define HW 4096
#define NTILES 640
#define NPARTS 4
#define NQ (NTILES * NPARTS)     // 2560 quarter-tiles
#define NTOT_F 2621440.0f
#define EPS_V 1e-8f
#define LN2F 0.69314718055994530942f

#define SPARSITY_W 0.8f
#define CONC_W     1.5f
#define COORD_W    1.0f
#define BG_W       0.1f

__device__ float g_part[NTILES][NPARTS][12];
__device__ float g_tile_contrib[NTILES];
__device__ unsigned int g_tile_cnt[NTILES];   // zero-init; reset by finalizer
__device__ unsigned int g_done = 0;

__device__ __forceinline__ float fast_tanh(float x) {
    float r;
    asm("tanh.approx.f32 %0, %1;" : "=f"(r) : "f"(x));
    return r;
}
__device__ __forceinline__ float fast_lg2(float x) {
    float r;
    asm("lg2.approx.f32 %0, %1;" : "=f"(r) : "f"(x));
    return r;
}

// One CTA per QUARTER tile (16 rows): 128 threads, 8 px/thread.
// grid 2560 -> ~64 warps/SM resident; combine via fixed-slot publish +
// acq_rel counter; 4th arriver combines in fixed order (deterministic).
__global__ __launch_bounds__(128, 16)
void loss_kernel(const float4* __restrict__ pred,
                 const float4* __restrict__ tgt,
                 float* __restrict__ out) {
    __shared__ float warp_red[4][12];

    const int q    = blockIdx.x;          // [0,2560)
    const int tile = q >> 2;
    const int part = q & 3;
    const size_t base = (size_t)tile * (HW / 4) + (size_t)part * 256;

    const int tid  = threadIdx.x;         // [0,128)
    const int lane = tid & 31;
    const int wid  = tid >> 5;            // [0,4)

    // elem j (in tile) = part*1024 + 4*(tid + 128k) + c, k=0..1:
    //   col = ((4*tid)&63) + c  (k-invariant)
    //   row = 16*part + (tid>>4) + 8k
    const float c0f = (float)((tid * 4) & 63);
    const float y0f = (float)((tid >> 4) + 16 * part);

    const float4* __restrict__ P = pred + base;
    const float4* __restrict__ T = tgt  + base;

    // front-load: 4 LDG.128 in flight
    float4 X0 = P[tid], X1 = P[tid + 128];
    float4 T0 = T[tid], T1 = T[tid + 128];

    float S = 0.f, S1 = 0.f, Ts = 0.f, Ts1 = 0.f;
    float wxp = 0.f, wxt = 0.f;
    float focA = 0.f, foc2 = 0.f, bg = 0.f;
    float plogA = 0.f, plg2 = 0.f, mxh2 = -1.f;

    #pragma unroll
    for (int k = 0; k < 2; k++) {
        float xv[4], tv[4];
        if (k == 0) { xv[0]=X0.x; xv[1]=X0.y; xv[2]=X0.z; xv[3]=X0.w;
                      tv[0]=T0.x; tv[1]=T0.y; tv[2]=T0.z; tv[3]=T0.w; }
        else        { xv[0]=X1.x; xv[1]=X1.y; xv[2]=X1.z; xv[3]=X1.w;
                      tv[0]=T1.x; tv[1]=T1.y; tv[2]=T1.z; tv[3]=T1.w; }
        float pv[4];
        #pragma unroll
        for (int c = 0; c < 4; c++) {
            float x  = xv[c];
            float t  = tv[c];
            float h2 = fast_tanh(0.5f * x);          // 2p-1
            float p  = fmaf(0.5f, h2, 0.5f);
            pv[c] = p;
            float pm  = fmaf(0.5f, fabsf(h2), 0.5f); // sigmoid(|x|)
            float l2p = fast_lg2(pm);                // log2 sigmoid(|x|) <= 0
            float bceA = fmaf(-x, t, fmaxf(x, 0.f));
            float om   = fabsf(t - p);               // 1 - p_t (t in {0,1})
            float om2  = om * om;
            focA = fmaf(om2, bceA, focA);
            foc2 = fmaf(om2, l2p,  foc2);
            bg   = fmaf(om2, 1.f - t, bg);
            plogA = fmaf(p, fminf(x, 0.f), plogA);
            plg2  = fmaf(p, l2p, plg2);
            mxh2  = fmaxf(mxh2, h2);
        }
        float gs = (pv[0] + pv[1]) + (pv[2] + pv[3]);
        float gw = fmaf(3.f, pv[3], fmaf(2.f, pv[2], pv[1]));
        float gt = (tv[0] + tv[1]) + (tv[2] + tv[3]);
        float gu = fmaf(3.f, tv[3], fmaf(2.f, tv[2], tv[1]));
        S   += gs;  wxp += gw;
        Ts  += gt;  wxt += gu;
        if (k == 1) { S1 = gs; Ts1 = gt; }
    }

    float pxs = fmaf(c0f, S,  wxp);
    float pys = fmaf(y0f, S,  8.f * S1);    // rows: y0 + 8k
    float txs = fmaf(c0f, Ts, wxt);
    float tys = fmaf(y0f, Ts, 8.f * Ts1);
    float mx  = fmaf(0.5f, mxh2, 0.5f);

    // warp butterfly: 11 sums + 1 max
    const unsigned FULL = 0xffffffffu;
    #pragma unroll
    for (int o = 16; o; o >>= 1) {
        S     += __shfl_xor_sync(FULL, S,     o);
        Ts    += __shfl_xor_sync(FULL, Ts,    o);
        pxs   += __shfl_xor_sync(FULL, pxs,   o);
        pys   += __shfl_xor_sync(FULL, pys,   o);
        txs   += __shfl_xor_sync(FULL, txs,   o);
        tys   += __shfl_xor_sync(FULL, tys,   o);
        focA  += __shfl_xor_sync(FULL, focA,  o);
        foc2  += __shfl_xor_sync(FULL, foc2,  o);
        bg    += __shfl_xor_sync(FULL, bg,    o);
        plogA += __shfl_xor_sync(FULL, plogA, o);
        plg2  += __shfl_xor_sync(FULL, plg2,  o);
        mx     = fmaxf(mx, __shfl_xor_sync(FULL, mx, o));
    }
    if (lane == 0) {
        warp_red[wid][0]  = S;     warp_red[wid][1]  = Ts;
        warp_red[wid][2]  = pxs;   warp_red[wid][3]  = pys;
        warp_red[wid][4]  = txs;   warp_red[wid][5]  = tys;
        warp_red[wid][6]  = focA;  warp_red[wid][7]  = foc2;
        warp_red[wid][8]  = bg;    warp_red[wid][9]  = plogA;
        warp_red[wid][10] = plg2;  warp_red[wid][11] = mx;
    }
    __syncthreads();
    if (wid != 0) return;          // bar counts non-exited threads (sm_70+)

    // warp 0: cross-warp combine (lanes 0-3 hold warp rows)
    float a[12];
    if (lane < 4) {
        #pragma unroll
        for (int i = 0; i < 12; i++) a[i] = warp_red[lane][i];
    } else {
        #pragma unroll
        for (int i = 0; i < 12; i++) a[i] = 0.f;
    }
    #pragma unroll
    for (int o = 2; o; o >>= 1) {
        #pragma unroll
        for (int i = 0; i < 11; i++) a[i] += __shfl_xor_sync(FULL, a[i], o);
        a[11] = fmaxf(a[11], __shfl_xor_sync(FULL, a[11], o));
    }

    // publish this quarter's stats + bump tile counter
    unsigned int r = 0;
    if (lane == 0) {
        #pragma unroll
        for (int i = 0; i < 12; i++) g_part[tile][part][i] = a[i];
        asm volatile("atom.add.acq_rel.gpu.u32 %0, [%1], 1;"
                     : "=r"(r) : "l"(&g_tile_cnt[tile]) : "memory");
    }
    r = __shfl_sync(FULL, r, 0);
    if (r != NPARTS - 1) return;   // not the last part of this tile

    // 4th arriver: combine parts in FIXED order (deterministic), finalize tile
    unsigned int prev = 0;
    if (lane == 0) {
        float b[12];
        #pragma unroll
        for (int i = 0; i < 12; i++) b[i] = g_part[tile][0][i];
        #pragma unroll
        for (int pp = 1; pp < NPARTS; pp++) {
            #pragma unroll
            for (int i = 0; i < 11; i++) b[i] += g_part[tile][pp][i];
            b[11] = fmaxf(b[11], g_part[tile][pp][11]);
        }
        g_tile_cnt[tile] = 0;      // reset for next graph replay

        float foc  = fmaf(-LN2F, b[7],  b[6]);
        float plog = fmaf( LN2F, b[10], b[9]);
        float Sp  = b[0] + EPS_V;
        float inv = 1.f / Sp;
        float ent = inv * (b[0] * logf(Sp) - plog);
        float ts  = b[1] + EPS_V;
        float px  = b[2] * inv, py = b[3] * inv;
        float tx  = b[4] / ts,  ty = b[5] / ts;
        float dx  = px - tx,    dy = py - ty;
        float coord = sqrtf(dx * dx + dy * dy);
        float conc  = 1.f - b[11];

        g_tile_contrib[tile] =
            (foc + BG_W * b[8]) * (1.f / NTOT_F) +
            (SPARSITY_W * ent + CONC_W * conc + COORD_W * coord) * (1.f / (float)NTILES);

        asm volatile("atom.add.acq_rel.gpu.u32 %0, [%1], 1;"
                     : "=r"(prev) : "l"(&g_done) : "memory");
    }
    prev = __shfl_sync(FULL, prev, 0);

    if (prev == NTILES - 1) {
        // very last finalizer: warp 0 reduces all 640 contributions (fixed order)
        float v = 0.f;
        #pragma unroll
        for (int i = 0; i < 20; i++)            // 640 / 32
            v += g_tile_contrib[lane + 32 * i];
        #pragma unroll
        for (int o = 16; o; o >>= 1)
            v += __shfl_xor_sync(FULL, v, o);
        if (lane == 0) {
            out[0] = v;
            g_done = 0;   // reset for next graph replay
        }
    }
}

extern "C" void kernel_launch(void* const* d_in, const int* in_sizes, int n_in,
                              void* d_out, int out_size) {
    const float4* pred = (const float4*)d_in[0];
    const float4* tgt  = (const float4*)d_in[1];
    float* out = (float*)d_out;
    loss_kernel<<<NQ, 128>>>(pred, tgt, out);
}

// round 14
// speedup vs baseline: 1.1594x; 1.1594x over previous
#include <cuda_runtime.h>
#include <cstdint>
#include <math.h>

#define HW 4096
#define NTILES 640
#define NTOT_F 2621440.0f
#define EPS_V 1e-8f
#define LN2F 0.69314718055994530942f

#define SPARSITY_W 0.8f
#define CONC_W     1.5f
#define COORD_W    1.0f
#define BG_W       0.1f

#define TILE_BYTES 16384u

__device__ float g_tile_contrib[NTILES];
__device__ unsigned int g_done = 0;

__device__ __forceinline__ float fast_tanh(float x) {
    float r;
    asm("tanh.approx.f32 %0, %1;" : "=f"(r) : "f"(x));
    return r;
}
__device__ __forceinline__ float fast_lg2(float x) {
    float r;
    asm("lg2.approx.f32 %0, %1;" : "=f"(r) : "f"(x));
    return r;
}
__device__ __forceinline__ unsigned int smem_u32(const void* p) {
    unsigned int a;
    asm("{ .reg .u64 t; cvta.to.shared.u64 t, %1; cvt.u32.u64 %0, t; }"
        : "=r"(a) : "l"(p));
    return a;
}
__device__ __forceinline__ void mbar_wait(unsigned int addr, unsigned int parity) {
    asm volatile(
        "{\n\t"
        ".reg .pred P;\n\t"
        "WAIT_%=:\n\t"
        "mbarrier.try_wait.parity.acquire.cta.shared::cta.b64 P, [%0], %1, 0x989680;\n\t"
        "@P bra DONE_%=;\n\t"
        "bra WAIT_%=;\n\t"
        "DONE_%=:\n\t"
        "}"
        :: "r"(addr), "r"(parity) : "memory");
}

// One CTA per tile: 128 threads. Whole 16KB+16KB tile fetched by ONE pair of
// cp.async.bulk copies (no per-thread LDG burst -> no cross-CTA L1tex-queue
// spread). Compute reads smem via LDS.128.
__global__ __launch_bounds__(128, 5)
void loss_kernel(const float* __restrict__ pred,
                 const float* __restrict__ tgt,
                 float* __restrict__ out) {
    __shared__ alignas(128) float sp[HW];     // 16 KB pred tile
    __shared__ alignas(128) float st[HW];     // 16 KB tgt tile
    __shared__ alignas(8) unsigned long long mbar;
    __shared__ float warp_red[4][12];
    __shared__ bool is_last;

    const int tile = blockIdx.x;
    const int tid  = threadIdx.x;          // [0,128)
    const int lane = tid & 31;
    const int wid  = tid >> 5;             // [0,4)

    const unsigned int mb = smem_u32(&mbar);
    if (tid == 0)
        asm volatile("mbarrier.init.shared.b64 [%0], 1;" :: "r"(mb) : "memory");
    __syncthreads();
    if (tid == 0) {
        asm volatile("mbarrier.arrive.expect_tx.shared.b64 _, [%0], %1;"
                     :: "r"(mb), "r"(2u * TILE_BYTES) : "memory");
        const float* gp = pred + (size_t)tile * HW;
        const float* gt = tgt  + (size_t)tile * HW;
        asm volatile(
            "cp.async.bulk.shared::cta.global.mbarrier::complete_tx::bytes "
            "[%0], [%1], %2, [%3];"
            :: "r"(smem_u32(sp)), "l"(gp), "r"(TILE_BYTES), "r"(mb) : "memory");
        asm volatile(
            "cp.async.bulk.shared::cta.global.mbarrier::complete_tx::bytes "
            "[%0], [%1], %2, [%3];"
            :: "r"(smem_u32(st)), "l"(gt), "r"(TILE_BYTES), "r"(mb) : "memory");
    }
    mbar_wait(mb, 0);

    // elem j = 4*(tid + 128k) + c, k=0..7:
    //   col = ((4*tid)&63) + c  (k-invariant);  row = (tid>>4) + 8k
    const float c0f = (float)((tid * 4) & 63);
    const float y0f = (float)(tid >> 4);

    const float4* SP4 = (const float4*)sp;
    const float4* ST4 = (const float4*)st;

    float S = 0.f, Ts = 0.f;
    float wxp = 0.f, wyp = 0.f, wxt = 0.f, wyt = 0.f;
    float focA = 0.f, foc2 = 0.f, bg = 0.f;
    float plogA = 0.f, plg2 = 0.f, mxh2 = -1.f;

    #pragma unroll
    for (int k = 0; k < 8; k++) {
        float4 x4 = SP4[tid + 128 * k];
        float4 t4 = ST4[tid + 128 * k];
        float xv[4] = {x4.x, x4.y, x4.z, x4.w};
        float tv[4] = {t4.x, t4.y, t4.z, t4.w};
        float pv[4];
        #pragma unroll
        for (int c = 0; c < 4; c++) {
            float x  = xv[c];
            float t  = tv[c];
            float h2 = fast_tanh(0.5f * x);          // 2p-1
            float p  = fmaf(0.5f, h2, 0.5f);
            pv[c] = p;
            float pm  = fmaf(0.5f, fabsf(h2), 0.5f); // sigmoid(|x|)
            float l2p = fast_lg2(pm);                // log2 sigmoid(|x|) <= 0
            float bceA = fmaf(-x, t, fmaxf(x, 0.f));
            float om   = fabsf(t - p);               // 1 - p_t (t in {0,1})
            float om2  = om * om;
            focA = fmaf(om2, bceA, focA);
            foc2 = fmaf(om2, l2p,  foc2);
            bg   = fmaf(om2, 1.f - t, bg);           // p^2 when t==0
            plogA = fmaf(p, fminf(x, 0.f), plogA);
            plg2  = fmaf(p, l2p, plg2);
            mxh2  = fmaxf(mxh2, h2);
        }
        const float kf = (float)k;
        float gs = (pv[0] + pv[1]) + (pv[2] + pv[3]);
        float gw = fmaf(3.f, pv[3], fmaf(2.f, pv[2], pv[1]));
        S   += gs;
        wxp += gw;
        wyp  = fmaf(kf, gs, wyp);
        float gt = (tv[0] + tv[1]) + (tv[2] + tv[3]);
        float gu = fmaf(3.f, tv[3], fmaf(2.f, tv[2], tv[1]));
        Ts  += gt;
        wxt += gu;
        wyt  = fmaf(kf, gt, wyt);
    }

    float pxs = fmaf(c0f, S,  wxp);
    float pys = fmaf(y0f, S,  8.f * wyp);    // rows step by 8 per k
    float txs = fmaf(c0f, Ts, wxt);
    float tys = fmaf(y0f, Ts, 8.f * wyt);
    float mx  = fmaf(0.5f, mxh2, 0.5f);

    // warp butterfly: 11 sums + 1 max
    const unsigned FULL = 0xffffffffu;
    #pragma unroll
    for (int o = 16; o; o >>= 1) {
        S     += __shfl_xor_sync(FULL, S,     o);
        Ts    += __shfl_xor_sync(FULL, Ts,    o);
        pxs   += __shfl_xor_sync(FULL, pxs,   o);
        pys   += __shfl_xor_sync(FULL, pys,   o);
        txs   += __shfl_xor_sync(FULL, txs,   o);
        tys   += __shfl_xor_sync(FULL, tys,   o);
        focA  += __shfl_xor_sync(FULL, focA,  o);
        foc2  += __shfl_xor_sync(FULL, foc2,  o);
        bg    += __shfl_xor_sync(FULL, bg,    o);
        plogA += __shfl_xor_sync(FULL, plogA, o);
        plg2  += __shfl_xor_sync(FULL, plg2,  o);
        mx     = fmaxf(mx, __shfl_xor_sync(FULL, mx, o));
    }
    if (lane == 0) {
        warp_red[wid][0]  = S;     warp_red[wid][1]  = Ts;
        warp_red[wid][2]  = pxs;   warp_red[wid][3]  = pys;
        warp_red[wid][4]  = txs;   warp_red[wid][5]  = tys;
        warp_red[wid][6]  = focA;  warp_red[wid][7]  = foc2;
        warp_red[wid][8]  = bg;    warp_red[wid][9]  = plogA;
        warp_red[wid][10] = plg2;  warp_red[wid][11] = mx;
    }
    __syncthreads();

    // cross-warp combine: 4 lanes of warp 0
    if (wid == 0 && lane < 4) {
        float a[12];
        #pragma unroll
        for (int i = 0; i < 12; i++) a[i] = warp_red[lane][i];
        const unsigned M4 = 0x0000000fu;
        #pragma unroll
        for (int o = 2; o; o >>= 1) {
            #pragma unroll
            for (int i = 0; i < 11; i++) a[i] += __shfl_xor_sync(M4, a[i], o);
            a[11] = fmaxf(a[11], __shfl_xor_sync(M4, a[11], o));
        }
        if (lane == 0) {
            float foc  = fmaf(-LN2F, a[7],  a[6]);   // focA - ln2*foc2
            float plog = fmaf( LN2F, a[10], a[9]);   // plogA + ln2*plg2

            float Sp  = a[0] + EPS_V;
            float inv = 1.f / Sp;
            float ent = inv * (a[0] * logf(Sp) - plog);
            float ts  = a[1] + EPS_V;
            float px  = a[2] * inv, py = a[3] * inv;
            float tx  = a[4] / ts,  ty = a[5] / ts;
            float dx  = px - tx,    dy = py - ty;
            float coord = sqrtf(dx * dx + dy * dy);
            float conc  = 1.f - a[11];

            g_tile_contrib[tile] =
                (foc + BG_W * a[8]) * (1.f / NTOT_F) +
                (SPARSITY_W * ent + CONC_W * conc + COORD_W * coord) * (1.f / (float)NTILES);

            __threadfence();
            unsigned r = atomicAdd(&g_done, 1u);
            is_last = (r == NTILES - 1);
        }
    }
    __syncthreads();

    if (is_last) {
        __threadfence();
        float v = 0.f;
        #pragma unroll
        for (int i = 0; i < 5; i++)                // 640 / 128
            v += g_tile_contrib[tid + 128 * i];
        #pragma unroll
        for (int o = 16; o; o >>= 1)
            v += __shfl_xor_sync(FULL, v, o);
        if (lane == 0) warp_red[wid][0] = v;
        __syncthreads();
        if (tid == 0) {
            float s = (warp_red[0][0] + warp_red[1][0])
                    + (warp_red[2][0] + warp_red[3][0]);
            out[0] = s;
            g_done = 0;   // reset for graph replay
        }
    }
}

extern "C" void kernel_launch(void* const* d_in, const int* in_sizes, int n_in,
                              void* d_out, int out_size) {
    const float* pred = (const float*)d_in[0];
    const float* tgt  = (const float*)d_in[1];
    float* out = (float*)d_out;
    loss_kernel<<<NTILES, 128>>>(pred, tgt, out);
}

// round 15
// speedup vs baseline: 1.1940x; 1.0299x over previous
#include <cuda_runtime.h>
#include <cstdint>
#include <math.h>

#define HW 4096
#define NTILES 640
#define NTOT_F 2621440.0f
#define EPS_V 1e-8f
#define LN2F 0.69314718055994530942f

#define SPARSITY_W 0.8f
#define CONC_W     1.5f
#define COORD_W    1.0f
#define BG_W       0.1f

__device__ float g_tile_contrib[NTILES];
__device__ unsigned int g_done = 0;

__device__ __forceinline__ float fast_tanh(float x) {
    float r;
    asm("tanh.approx.f32 %0, %1;" : "=f"(r) : "f"(x));
    return r;
}
__device__ __forceinline__ float fast_lg2(float x) {
    float r;
    asm("lg2.approx.f32 %0, %1;" : "=f"(r) : "f"(x));
    return r;
}

// One CTA per tile: 256 threads, 16 px/thread (8 front-issued LDG.128).
// 5 CTAs/SM -> whole grid resident; 8.6 warps/SMSP for latency hiding.
__global__ __launch_bounds__(256, 5)
void loss_kernel(const float4* __restrict__ pred,
                 const float4* __restrict__ tgt,
                 float* __restrict__ out) {
    __shared__ float warp_red[8][12];
    __shared__ bool is_last;

    const int tile = blockIdx.x;
    const float4* __restrict__ P = pred + (size_t)tile * (HW / 4);
    const float4* __restrict__ T = tgt  + (size_t)tile * (HW / 4);

    const int tid  = threadIdx.x;          // [0,256)
    const int lane = tid & 31;
    const int wid  = tid >> 5;             // [0,8)

    // elem j = 4*(tid + 256k) + c, k=0..3:
    //   col = ((4*tid)&63) + c  (k-invariant);  row = (tid>>4) + 16k
    const float c0f = (float)((tid * 4) & 63);
    const float y0f = (float)(tid >> 4);

    // front-load everything: 8 x LDG.128 in flight
    float4 X[4], Tv4[4];
    #pragma unroll
    for (int k = 0; k < 4; k++) X[k]   = P[tid + 256 * k];
    #pragma unroll
    for (int k = 0; k < 4; k++) Tv4[k] = T[tid + 256 * k];

    float S = 0.f, Ts = 0.f;
    float wxp = 0.f, wyp = 0.f, wxt = 0.f, wyt = 0.f;
    float focA = 0.f, foc2 = 0.f, bg = 0.f;
    float plogA = 0.f, plg2 = 0.f, mxh2 = -1.f;

    #pragma unroll
    for (int k = 0; k < 4; k++) {
        float xv[4] = {X[k].x,   X[k].y,   X[k].z,   X[k].w};
        float tv[4] = {Tv4[k].x, Tv4[k].y, Tv4[k].z, Tv4[k].w};
        float pv[4];
        #pragma unroll
        for (int c = 0; c < 4; c++) {
            float x  = xv[c];
            float t  = tv[c];
            float h2 = fast_tanh(0.5f * x);          // 2p-1
            float p  = fmaf(0.5f, h2, 0.5f);
            pv[c] = p;
            float pm  = fmaf(0.5f, fabsf(h2), 0.5f); // sigmoid(|x|)
            float l2p = fast_lg2(pm);                // log2 sigmoid(|x|) <= 0
            float bceA = fmaf(-x, t, fmaxf(x, 0.f));
            float om   = fabsf(t - p);               // 1 - p_t (t in {0,1})
            float om2  = om * om;
            focA = fmaf(om2, bceA, focA);
            foc2 = fmaf(om2, l2p,  foc2);
            bg   = fmaf(om2, 1.f - t, bg);           // p^2 when t==0
            plogA = fmaf(p, fminf(x, 0.f), plogA);
            plg2  = fmaf(p, l2p, plg2);
            mxh2  = fmaxf(mxh2, h2);
        }
        const float kf = (float)k;
        float gs = (pv[0] + pv[1]) + (pv[2] + pv[3]);
        float gw = fmaf(3.f, pv[3], fmaf(2.f, pv[2], pv[1]));
        S   += gs;
        wxp += gw;
        wyp  = fmaf(kf, gs, wyp);
        float gt = (tv[0] + tv[1]) + (tv[2] + tv[3]);
        float gu = fmaf(3.f, tv[3], fmaf(2.f, tv[2], tv[1]));
        Ts  += gt;
        wxt += gu;
        wyt  = fmaf(kf, gt, wyt);
    }

    float pxs = fmaf(c0f, S,  wxp);
    float pys = fmaf(y0f, S,  16.f * wyp);   // rows step by 16 per k
    float txs = fmaf(c0f, Ts, wxt);
    float tys = fmaf(y0f, Ts, 16.f * wyt);
    float mx  = fmaf(0.5f, mxh2, 0.5f);

    // warp butterfly: 11 sums + 1 max
    const unsigned FULL = 0xffffffffu;
    #pragma unroll
    for (int o = 16; o; o >>= 1) {
        S     += __shfl_xor_sync(FULL, S,     o);
        Ts    += __shfl_xor_sync(FULL, Ts,    o);
        pxs   += __shfl_xor_sync(FULL, pxs,   o);
        pys   += __shfl_xor_sync(FULL, pys,   o);
        txs   += __shfl_xor_sync(FULL, txs,   o);
        tys   += __shfl_xor_sync(FULL, tys,   o);
        focA  += __shfl_xor_sync(FULL, focA,  o);
        foc2  += __shfl_xor_sync(FULL, foc2,  o);
        bg    += __shfl_xor_sync(FULL, bg,    o);
        plogA += __shfl_xor_sync(FULL, plogA, o);
        plg2  += __shfl_xor_sync(FULL, plg2,  o);
        mx     = fmaxf(mx, __shfl_xor_sync(FULL, mx, o));
    }
    if (lane == 0) {
        warp_red[wid][0]  = S;     warp_red[wid][1]  = Ts;
        warp_red[wid][2]  = pxs;   warp_red[wid][3]  = pys;
        warp_red[wid][4]  = txs;   warp_red[wid][5]  = tys;
        warp_red[wid][6]  = focA;  warp_red[wid][7]  = foc2;
        warp_red[wid][8]  = bg;    warp_red[wid][9]  = plogA;
        warp_red[wid][10] = plg2;  warp_red[wid][11] = mx;
    }
    __syncthreads();

    // cross-warp combine: 8 lanes of warp 0
    if (wid == 0 && lane < 8) {
        float a[12];
        #pragma unroll
        for (int i = 0; i < 12; i++) a[i] = warp_red[lane][i];
        const unsigned M8 = 0x000000ffu;
        #pragma unroll
        for (int o = 4; o; o >>= 1) {
            #pragma unroll
            for (int i = 0; i < 11; i++) a[i] += __shfl_xor_sync(M8, a[i], o);
            a[11] = fmaxf(a[11], __shfl_xor_sync(M8, a[11], o));
        }
        if (lane == 0) {
            float foc  = fmaf(-LN2F, a[7],  a[6]);   // focA - ln2*foc2
            float plog = fmaf( LN2F, a[10], a[9]);   // plogA + ln2*plg2

            float Sp  = a[0] + EPS_V;
            float inv = 1.f / Sp;
            float ent = inv * (a[0] * logf(Sp) - plog);
            float ts  = a[1] + EPS_V;
            float px  = a[2] * inv, py = a[3] * inv;
            float tx  = a[4] / ts,  ty = a[5] / ts;
            float dx  = px - tx,    dy = py - ty;
            float coord = sqrtf(dx * dx + dy * dy);
            float conc  = 1.f - a[11];

            g_tile_contrib[tile] =
                (foc + BG_W * a[8]) * (1.f / NTOT_F) +
                (SPARSITY_W * ent + CONC_W * conc + COORD_W * coord) * (1.f / (float)NTILES);

            __threadfence();
            unsigned r = atomicAdd(&g_done, 1u);
            is_last = (r == NTILES - 1);
        }
    }
    __syncthreads();

    if (is_last) {
        __threadfence();
        float v = 0.f;
        if (tid < 128) {
            #pragma unroll
            for (int i = 0; i < 5; i++)            // 640 / 128
                v += g_tile_contrib[tid + 128 * i];
        }
        #pragma unroll
        for (int o = 16; o; o >>= 1)
            v += __shfl_xor_sync(FULL, v, o);
        if (lane == 0) warp_red[wid][0] = v;
        __syncthreads();
        if (tid == 0) {
            float s = (warp_red[0][0] + warp_red[1][0])
                    + (warp_red[2][0] + warp_red[3][0]);
            out[0] = s;
            g_done = 0;   // reset for graph replay
        }
    }
}

extern "C" void kernel_launch(void* const* d_in, const int* in_sizes, int n_in,
                              void* d_out, int out_size) {
    const float4* pred = (const float4*)d_in[0];
    const float4* tgt  = (const float4*)d_in[1];
    float* out = (float*)d_out;
    loss_kernel<<<NTILES, 256>>>(pred, tgt, out);
}